// round 1
// baseline (speedup 1.0000x reference)
#include <cuda_runtime.h>
#include <cuda_fp16.h>

#define NB 32
#define NN 1024
#define NM 1024
#define EPSI 0.1f
#define CSH 2.7725887222397811f   /* ln(16) */
#define LN2F 0.6931471805599453f

// K' = 16 * exp(-D/eps) stored as fp16, packed 4-per-uint2. 64 MB — L2 resident.
__device__ uint2 g_K[(size_t)NB * NN * NM / 4];
__device__ float g_s[NB * NN];        // row sums  s_i = sum_j K v_j
__device__ float g_t0[NB * NM];       // ping-pong col sums t_j = sum_i K u_i
__device__ float g_t1[NB * NM];

// ---------------------------------------------------------------------------
// Convert: K' = exp(ln16 - 10*D) -> fp16. Also init g_t0 = 1 (v0 = 1), out = 0.
// grid: 32768 x 256, each thread converts 4 consecutive floats.
// ---------------------------------------------------------------------------
__global__ __launch_bounds__(256) void k_convert(const float4* __restrict__ D4,
                                                 float* __restrict__ out) {
    int idx = blockIdx.x * 256 + threadIdx.x;      // 0 .. 8388607
    float4 d = D4[idx];
    float a = __expf(fmaf(d.x, -10.0f, CSH));
    float b = __expf(fmaf(d.y, -10.0f, CSH));
    float c = __expf(fmaf(d.z, -10.0f, CSH));
    float e = __expf(fmaf(d.w, -10.0f, CSH));
    __half2 h0 = __floats2half2_rn(a, b);
    __half2 h1 = __floats2half2_rn(c, e);
    uint2 p;
    p.x = *reinterpret_cast<unsigned int*>(&h0);
    p.y = *reinterpret_cast<unsigned int*>(&h1);
    g_K[idx] = p;
    if (idx < NB * NM) g_t0[idx] = 1.0f;
    if (idx == 0) *out = 0.0f;
}

// ---------------------------------------------------------------------------
// Row pass: s_i = sum_j K_ij * v_j, v_j = 1/tIn_j. Also zeroes tOut for the
// col pass that follows (ping-pong buffer last read one iteration ago — safe).
// grid: 4096 blocks x 256 threads; 8 warps/block, one warp per row.
// ---------------------------------------------------------------------------
__global__ __launch_bounds__(256) void k_row(int parity) {
    const float* __restrict__ tIn  = parity ? g_t1 : g_t0;
    float* __restrict__       tOut = parity ? g_t0 : g_t1;
    __shared__ float4 sv[NM / 4];

    int tid   = threadIdx.x;
    int grow0 = blockIdx.x * 8;          // first global row of this block
    int b     = grow0 >> 10;             // batch (8 rows never cross a batch)

    if (tid < 8) tOut[blockIdx.x * 8 + tid] = 0.0f;   // 4096*8 = 32768 ✓

    float4 t4 = reinterpret_cast<const float4*>(tIn)[b * (NM / 4) + tid];
    sv[tid] = make_float4(1.0f / t4.x, 1.0f / t4.y, 1.0f / t4.z, 1.0f / t4.w);
    __syncthreads();

    int warp = tid >> 5, lane = tid & 31;
    int row  = grow0 + warp;
    const uint2* __restrict__ Kr = g_K + (size_t)row * (NM / 4);

    float acc = 0.0f;
#pragma unroll
    for (int it = 0; it < 8; ++it) {
        int q = lane + it * 32;
        uint2 p = Kr[q];
        __half2 h0 = *reinterpret_cast<__half2*>(&p.x);
        __half2 h1 = *reinterpret_cast<__half2*>(&p.y);
        float2 f0 = __half22float2(h0);
        float2 f1 = __half22float2(h1);
        float4 v = sv[q];
        acc = fmaf(f0.x, v.x, acc);
        acc = fmaf(f0.y, v.y, acc);
        acc = fmaf(f1.x, v.z, acc);
        acc = fmaf(f1.y, v.w, acc);
    }
#pragma unroll
    for (int o = 16; o > 0; o >>= 1) acc += __shfl_xor_sync(0xffffffffu, acc, o);
    if (lane == 0) g_s[row] = acc;
}

// ---------------------------------------------------------------------------
// Col pass: tOut_j += sum_i K_ij * u_i over a 64-row chunk, u_i = 1/s_i.
// grid: 512 blocks (32 batches x 16 row-chunks) x 256 threads;
// each thread owns 4 consecutive columns, accumulates locally, one atomicAdd x4.
// ---------------------------------------------------------------------------
__global__ __launch_bounds__(256) void k_col(int parity) {
    float* __restrict__ tOut = parity ? g_t0 : g_t1;
    __shared__ float su[64];

    int tid = threadIdx.x;
    int b   = blockIdx.x >> 4;
    int i0  = (blockIdx.x & 15) * 64;

    if (tid < 64) su[tid] = 1.0f / g_s[b * NN + i0 + tid];
    __syncthreads();

    const uint2* __restrict__ Kb = g_K + ((size_t)(b * NN + i0)) * (NM / 4) + tid;

    float4 acc = make_float4(0.f, 0.f, 0.f, 0.f);
#pragma unroll 4
    for (int i = 0; i < 64; ++i) {
        float u = su[i];
        uint2 p = Kb[(size_t)i * (NM / 4)];
        __half2 h0 = *reinterpret_cast<__half2*>(&p.x);
        __half2 h1 = *reinterpret_cast<__half2*>(&p.y);
        float2 f0 = __half22float2(h0);
        float2 f1 = __half22float2(h1);
        acc.x = fmaf(f0.x, u, acc.x);
        acc.y = fmaf(f0.y, u, acc.y);
        acc.z = fmaf(f1.x, u, acc.z);
        acc.w = fmaf(f1.y, u, acc.w);
    }
    float* to = tOut + b * NM + tid * 4;
    atomicAdd(to + 0, acc.x);
    atomicAdd(to + 1, acc.y);
    atomicAdd(to + 2, acc.z);
    atomicAdd(to + 3, acc.w);
}

// ---------------------------------------------------------------------------
// Final: loss = (eps/32) * sum_ij u_i * v_j * K'_ij * (ln16 - ln K'_ij)
// (D = eps*(ln16 - ln K'); u = 1/s from last row pass, v = 1/t from last col pass)
// grid: 4096 x 256, warp per row, one atomicAdd per block.
// ---------------------------------------------------------------------------
__global__ __launch_bounds__(256) void k_final(float* __restrict__ out) {
    const float* __restrict__ tIn = g_t0;   // 20 iterations -> final t in g_t0
    __shared__ float4 sv[NM / 4];
    __shared__ float part[8];

    int tid   = threadIdx.x;
    int grow0 = blockIdx.x * 8;
    int b     = grow0 >> 10;

    float4 t4 = reinterpret_cast<const float4*>(tIn)[b * (NM / 4) + tid];
    sv[tid] = make_float4(1.0f / t4.x, 1.0f / t4.y, 1.0f / t4.z, 1.0f / t4.w);
    __syncthreads();

    int warp = tid >> 5, lane = tid & 31;
    int row  = grow0 + warp;
    const uint2* __restrict__ Kr = g_K + (size_t)row * (NM / 4);

    float acc = 0.0f;
#pragma unroll
    for (int it = 0; it < 8; ++it) {
        int q = lane + it * 32;
        uint2 p = Kr[q];
        __half2 h0 = *reinterpret_cast<__half2*>(&p.x);
        __half2 h1 = *reinterpret_cast<__half2*>(&p.y);
        float2 f0 = __half22float2(h0);
        float2 f1 = __half22float2(h1);
        float4 v = sv[q];
        float t0 = f0.x * fmaf(-LN2F, __log2f(f0.x), CSH);
        float t1 = f0.y * fmaf(-LN2F, __log2f(f0.y), CSH);
        float t2 = f1.x * fmaf(-LN2F, __log2f(f1.x), CSH);
        float t3 = f1.y * fmaf(-LN2F, __log2f(f1.y), CSH);
        acc = fmaf(t0, v.x, acc);
        acc = fmaf(t1, v.y, acc);
        acc = fmaf(t2, v.z, acc);
        acc = fmaf(t3, v.w, acc);
    }
#pragma unroll
    for (int o = 16; o > 0; o >>= 1) acc += __shfl_xor_sync(0xffffffffu, acc, o);
    if (lane == 0) part[warp] = acc * (1.0f / g_s[row]);
    __syncthreads();
    if (tid == 0) {
        float s2 = 0.0f;
#pragma unroll
        for (int w = 0; w < 8; ++w) s2 += part[w];
        atomicAdd(out, s2 * (EPSI / (float)NB));
    }
}

// ---------------------------------------------------------------------------
extern "C" void kernel_launch(void* const* d_in, const int* in_sizes, int n_in,
                              void* d_out, int out_size) {
    const float4* D4 = reinterpret_cast<const float4*>(d_in[0]);
    float* out = reinterpret_cast<float*>(d_out);

    k_convert<<<32768, 256>>>(D4, out);
    for (int k = 0; k < 20; ++k) {
        int parity = k & 1;           // tIn = parity ? t1 : t0, tOut = other
        k_row<<<4096, 256>>>(parity);
        k_col<<<512, 256>>>(parity);
    }
    k_final<<<4096, 256>>>(out);
}